// round 17
// baseline (speedup 1.0000x reference)
#include <cuda_runtime.h>
#include <cstdint>

// Problem constants
#define TT   16
#define BB   512
#define NIN  3072
#define SS1  256
#define SS2  256
#define SS3  128
#define EE   8
#define DECAYF 0.95f
#define KCHUNK 512   // confirmed reference k-partition: 512-chunks, serial ascending fold
#define MM   (TT * BB)   // 8192

typedef unsigned long long ull;

// Persistent scratch (allocation-free: __device__ globals)
__device__ float g_H1[(size_t)EE * MM * SS1];   // 67 MB
__device__ float g_H2[(size_t)EE * MM * SS2];   // 67 MB
__device__ float g_H3[(size_t)EE * MM * SS3];   // 33 MB
__device__ float g_C1[(size_t)MM * SS1];        // 8.4 MB  (row-major [m][o])
__device__ float g_C2[(size_t)MM * SS2];        // 8.4 MB
__device__ ull   g_Xd [(size_t)NIN * MM];       // 201 MB  X  -> [k][m] (x,x) pairs
__device__ ull   g_C1d[(size_t)SS1 * MM];       // 17 MB   C1 -> [k][m] dup pairs
__device__ ull   g_C2d[(size_t)SS2 * MM];       // 17 MB
__device__ float g_W1t[(size_t)EE * NIN * SS1]; // 25 MB   W1 -> [e][k][n]
__device__ float g_W2t[(size_t)EE * SS1 * SS2]; // 2 MB
__device__ float g_W3t[(size_t)EE * SS2 * SS3]; // 1 MB

// ---- packed f32x2 helpers: each half is an independent rn op, bit-exact
//      vs the scalar serial chain (verified rel_err==0.0 since R11) -------
__device__ __forceinline__ ull fma2(ull a, ull b, ull c) {
    asm("fma.rn.f32x2 %0, %1, %2, %0;" : "+l"(c) : "l"(a), "l"(b));
    return c;
}
__device__ __forceinline__ ull add2(ull a, ull b) {
    ull r; asm("add.rn.f32x2 %0, %1, %2;" : "=l"(r) : "l"(a), "l"(b));
    return r;
}
__device__ __forceinline__ ull dup2(float x) {
    ull r; asm("mov.b64 %0, {%1, %1};" : "=l"(r) : "f"(x));
    return r;
}
__device__ __forceinline__ float2 unpk(ull a) {
    float2 r; asm("mov.b64 {%0, %1}, %2;" : "=f"(r.x), "=f"(r.y) : "l"(a));
    return r;
}
__device__ __forceinline__ void cpa16(uint32_t s, const void* g) {
    asm volatile("cp.async.ca.shared.global [%0], [%1], 16;" :: "r"(s), "l"(g));
}

// ---------------------------------------------------------------------------
// Batched transpose (plain float): src[z][R][C] -> dst[z][C][R].
// 32x32 tiles, 32x8 threads. R, C multiples of 32.
// ---------------------------------------------------------------------------
__global__ void transpose_b(const float* __restrict__ src,
                            float* __restrict__ dst, int R, int C) {
    __shared__ float t[32][33];
    const float* s = src + (size_t)blockIdx.z * R * C;
    float*       d = dst + (size_t)blockIdx.z * R * C;
    int c0 = blockIdx.x * 32, r0 = blockIdx.y * 32;
    int x = threadIdx.x, y = threadIdx.y;
    #pragma unroll
    for (int i = 0; i < 32; i += 8)
        t[y + i][x] = s[(size_t)(r0 + y + i) * C + c0 + x];
    __syncthreads();
    #pragma unroll
    for (int i = 0; i < 32; i += 8)
        d[(size_t)(c0 + y + i) * R + r0 + x] = t[x][y + i];
}

// ---------------------------------------------------------------------------
// Transpose + duplicate: src[R][C] float -> dst[C][R] ull, each (v,v).
// ---------------------------------------------------------------------------
__global__ void transpose_dup(const float* __restrict__ src,
                              ull* __restrict__ dst, int R, int C) {
    __shared__ float t[32][33];
    int c0 = blockIdx.x * 32, r0 = blockIdx.y * 32;
    int x = threadIdx.x, y = threadIdx.y;
    #pragma unroll
    for (int i = 0; i < 32; i += 8)
        t[y + i][x] = src[(size_t)(r0 + y + i) * C + c0 + x];
    __syncthreads();
    #pragma unroll
    for (int i = 0; i < 32; i += 8)
        dst[(size_t)(c0 + y + i) * R + r0 + x] = dup2(t[x][y + i]);
}

// ---------------------------------------------------------------------------
// Batched NT SGEMM, packed f32x2, k-chunked (PC=512) fp32 accumulation with
// REGISTER chunk fold:
//   per chunk: fresh accumulator accP, strictly ascending rn-FMA chain;
//   boundary: accC = rn(accC + accP), accP = 0 (first fold exact: accC==0).
//   Final store rn(accC + accP) (exact no-op when either side is 0).
//   Bit-identical to the confirmed reference partition.
// Xd: [K][M] ull, entry m = (x[m][k], x[m][k]).  Wt: [E][K][N] float.
// BM=32, BN template (256/128), BK=16, 256 threads = (ty 16) x (tx 16).
// Thread microtile: rows {2ty, 2ty+1} x cols [tx*2*TUX, +2*TUX) packed as
// column-pair ulls -> W operands natural LDS.128, X operands pre-dup'd
// broadcast LDS.128. Inner kk: 5 LDS.128 + 2*TUX fma2, ZERO MOVs.
// Ring-3 cp.async pipeline. M%32==0, N%BN==0, K%16==0, PC%16==0.
// ---------------------------------------------------------------------------
template<int BN>
__global__ void __launch_bounds__(256, 2) gemm_x2(
    const ull*   __restrict__ Xd,  // [K][M] dup'd
    const float* __restrict__ Wt,  // [E][K][N]
    float* __restrict__ H,         // [E][M][N]
    int M, int N, int K, int PC)
{
    constexpr int BK = 16, BM = 32;
    constexpr int TUX = BN / 32;               // col-pair ulls per thread (8/4)
    constexpr int XS_ULL  = BK * BM;           // 512 ull per stage
    constexpr int STG_FLT = XS_ULL * 2 + BK * BN;  // stage stride in floats
    constexpr int GPW = BN / 4;                // W cp.async granules per k-row
    constexpr int WGT = BK * GPW / 256;        // W granules per thread (4/2)
    extern __shared__ float smem[];            // 3 stages
    const uint32_t sb = (uint32_t)__cvta_generic_to_shared(smem);

    const int e  = blockIdx.z;
    const int m0 = blockIdx.x * BM;
    const int n0 = blockIdx.y * BN;
    float* Hp = H + (size_t)e * M * N;

    const int tid = threadIdx.x;
    const int ty  = tid >> 4;        // 0..15: rows 2ty, 2ty+1
    const int tx  = tid & 15;        // 0..15: cols tx*2*TUX ..

    ull accP[2][TUX], accC[2][TUX];
    #pragma unroll
    for (int r = 0; r < 2; r++)
        #pragma unroll
        for (int j = 0; j < TUX; j++) { accP[r][j] = 0ULL; accC[r][j] = 0ULL; }

    // cp.async one BK-tile (X-dup 4KB + W BK*BN*4) into ring stage s.
    auto copy_tile = [&](int k0, int s) {
        uint32_t xa = sb + (uint32_t)(s * STG_FLT) * 4;
        uint32_t wa = xa + XS_ULL * 8;
        {   // X: 256 granules of 16B, one per thread
            int kk = tid >> 4, mu = (tid & 15) * 2;
            cpa16(xa + (uint32_t)(kk * BM + mu) * 8,
                  Xd + (size_t)(k0 + kk) * M + m0 + mu);
        }
        const float* wsrc = Wt + ((size_t)e * K + k0) * N + n0;
        #pragma unroll
        for (int i = 0; i < WGT; i++) {
            int g  = tid + i * 256;
            int kk = g / GPW, nc = (g % GPW) * 4;
            cpa16(wa + (uint32_t)(kk * BN + nc) * 4,
                  wsrc + (size_t)kk * N + nc);
        }
        asm volatile("cp.async.commit_group;");
    };

    const int nt = K / BK;
    copy_tile(0, 0);
    if (nt > 1) copy_tile(BK, 1);

    for (int i = 0; i < nt; i++) {
        const int k0 = i * BK;
        if (i < nt - 1) asm volatile("cp.async.wait_group 1;");
        else            asm volatile("cp.async.wait_group 0;");
        __syncthreads();   // tile i visible; all warps done with stage (i+2)%3
        if (i + 2 < nt) copy_tile(k0 + 2 * BK, (i + 2) % 3);

        const ull*   Xb = reinterpret_cast<const ull*>(smem + (i % 3) * STG_FLT);
        const float* Wb = smem + (i % 3) * STG_FLT + 2 * XS_ULL;

        #pragma unroll
        for (int kk = 0; kk < BK; kk++) {   // strictly ascending k
            ulonglong2 xv = *reinterpret_cast<const ulonglong2*>(
                &Xb[kk * BM + 2 * ty]);                  // broadcast LDS.128
            ull wp[TUX];
            const ull* wr = reinterpret_cast<const ull*>(Wb + kk * BN) + tx * TUX;
            #pragma unroll
            for (int j = 0; j < TUX; j++) wp[j] = wr[j]; // LDS.128 x TUX/2
            #pragma unroll
            for (int j = 0; j < TUX; j++) {
                accP[0][j] = fma2(xv.x, wp[j], accP[0][j]);
                accP[1][j] = fma2(xv.y, wp[j], accP[1][j]);
            }
        }

        // 512-chunk boundary: fold into accC (serial ascending), reset accP.
        if (((k0 + BK) % PC) == 0) {
            #pragma unroll
            for (int r = 0; r < 2; r++)
                #pragma unroll
                for (int j = 0; j < TUX; j++) {
                    accC[r][j] = add2(accC[r][j], accP[r][j]);
                    accP[r][j] = 0ULL;
                }
        }
    }

    // Epilogue: final = accC + accP (exact no-op add on the zero side).
    #pragma unroll
    for (int r = 0; r < 2; r++) {
        float o[2 * TUX];
        #pragma unroll
        for (int j = 0; j < TUX; j++) {
            float2 v = unpk(add2(accC[r][j], accP[r][j]));
            o[2*j] = v.x; o[2*j+1] = v.y;                // adjacent columns
        }
        float* a = &Hp[(size_t)(m0 + 2 * ty + r) * N + n0 + tx * 2 * TUX];
        #pragma unroll
        for (int q = 0; q < TUX / 2; q++)
            *reinterpret_cast<float4*>(a + 4 * q) =
                make_float4(o[4*q], o[4*q+1], o[4*q+2], o[4*q+3]);
    }
}

// ---------------------------------------------------------------------------
// LIF scan over ALL timesteps, 4 elements per thread (float4 path).
//   v = rn(rn(v*0.95) + h) ; spk = (v>=1) ; v = rn(v - spk)
//   c = sum_e g[e]*spk ;  mean = (sum_t c) * 1/16  (both exact)
// ---------------------------------------------------------------------------
__global__ void lif_scan4(
    const float* __restrict__ H,    // [E][M][no]
    const float* __restrict__ g,
    float* __restrict__ Cout,       // [M][no] (null: skip)
    float* __restrict__ Omean,      // [B*no]
    int no)
{
    int n = BB * no;
    int i4 = (blockIdx.x * blockDim.x + threadIdx.x) * 4;
    if (i4 >= n) return;
    float gv[EE];
    #pragma unroll
    for (int e = 0; e < EE; e++) gv[e] = __ldg(&g[e]);
    float v[EE][4];
    #pragma unroll
    for (int e = 0; e < EE; e++)
        #pragma unroll
        for (int u = 0; u < 4; u++) v[e][u] = 0.f;
    float osum[4] = {0.f, 0.f, 0.f, 0.f};

    for (int t = 0; t < TT; t++) {
        float c[4] = {0.f, 0.f, 0.f, 0.f};
        #pragma unroll
        for (int e = 0; e < EE; e++) {
            float4 h = *reinterpret_cast<const float4*>(
                &H[((size_t)e * MM + (size_t)t * BB) * no + i4]);
            float hv[4] = {h.x, h.y, h.z, h.w};
            #pragma unroll
            for (int u = 0; u < 4; u++) {
                float vv  = __fadd_rn(__fmul_rn(v[e][u], DECAYF), hv[u]);
                float spk = (vv >= 1.0f) ? 1.0f : 0.0f;
                v[e][u] = __fsub_rn(vv, spk);
                c[u] = __fadd_rn(c[u], __fmul_rn(gv[e], spk));
            }
        }
        if (Cout)
            *reinterpret_cast<float4*>(&Cout[(size_t)t * n + i4]) =
                make_float4(c[0], c[1], c[2], c[3]);
        #pragma unroll
        for (int u = 0; u < 4; u++) osum[u] = __fadd_rn(osum[u], c[u]);
    }
    *reinterpret_cast<float4*>(&Omean[i4]) = make_float4(
        __fmul_rn(osum[0], 1.0f/(float)TT), __fmul_rn(osum[1], 1.0f/(float)TT),
        __fmul_rn(osum[2], 1.0f/(float)TT), __fmul_rn(osum[3], 1.0f/(float)TT));
}

// ---------------------------------------------------------------------------
extern "C" void kernel_launch(void* const* d_in, const int* in_sizes, int n_in,
                              void* d_out, int out_size) {
    const float* X  = (const float*)d_in[0];  // [16][512][3072]
    const float* W1 = (const float*)d_in[1];  // [8][256][3072]
    const float* W2 = (const float*)d_in[2];  // [8][256][256]
    const float* W3 = (const float*)d_in[3];  // [8][128][256]
    const float* g1 = (const float*)d_in[4];
    const float* g2 = (const float*)d_in[5];
    const float* g3 = (const float*)d_in[6];
    float* out = (float*)d_out;

    float *H1, *H2, *H3, *C1, *C2, *W1t, *W2t, *W3t;
    ull *Xd, *C1d, *C2d;
    cudaGetSymbolAddress((void**)&H1,  g_H1);
    cudaGetSymbolAddress((void**)&H2,  g_H2);
    cudaGetSymbolAddress((void**)&H3,  g_H3);
    cudaGetSymbolAddress((void**)&C1,  g_C1);
    cudaGetSymbolAddress((void**)&C2,  g_C2);
    cudaGetSymbolAddress((void**)&Xd,  g_Xd);
    cudaGetSymbolAddress((void**)&C1d, g_C1d);
    cudaGetSymbolAddress((void**)&C2d, g_C2d);
    cudaGetSymbolAddress((void**)&W1t, g_W1t);
    cudaGetSymbolAddress((void**)&W2t, g_W2t);
    cudaGetSymbolAddress((void**)&W3t, g_W3t);

    const int SMEM256 = 3 * (16 * 32 * 2 + 16 * 256) * 4;  // 60 KB
    const int SMEM128 = 3 * (16 * 32 * 2 + 16 * 128) * 4;  // 36 KB
    static bool attr_set = false;
    if (!attr_set) {
        cudaFuncSetAttribute(gemm_x2<256>,
            cudaFuncAttributeMaxDynamicSharedMemorySize, SMEM256);
        cudaFuncSetAttribute(gemm_x2<128>,
            cudaFuncAttributeMaxDynamicSharedMemorySize, SMEM128);
        attr_set = true;
    }

    const int n1 = BB * SS1, n2 = BB * SS2, n3 = BB * SS3;
    dim3 tb(32, 8);

    // Input-only transposes (independent; front-loaded).
    transpose_dup<<<dim3(NIN/32, MM/32),    tb>>>(X,  Xd,  MM,  NIN);
    transpose_b  <<<dim3(NIN/32, SS1/32, EE), tb>>>(W1, W1t, SS1, NIN);
    transpose_b  <<<dim3(SS1/32, SS2/32, EE), tb>>>(W2, W2t, SS2, SS1);
    transpose_b  <<<dim3(SS2/32, SS3/32, EE), tb>>>(W3, W3t, SS3, SS2);

    // ---- Stage 1: M=8192, N=256, K=3072, 512-chunk serial fold ----
    gemm_x2<256><<<dim3(MM/32, SS1/256, EE), 256, SMEM256>>>(
        Xd, W1t, H1, MM, SS1, NIN, KCHUNK);
    lif_scan4<<<(n1/4 + 255)/256, 256>>>(H1, g1, C1, out, SS1);

    // ---- Stage 2: K=256 < 512 -> single serial chain ----
    transpose_dup<<<dim3(SS1/32, MM/32), tb>>>(C1, C1d, MM, SS1);
    gemm_x2<256><<<dim3(MM/32, SS2/256, EE), 256, SMEM256>>>(
        C1d, W2t, H2, MM, SS2, SS1, KCHUNK);
    lif_scan4<<<(n2/4 + 255)/256, 256>>>(H2, g2, C2, out + n1, SS2);

    // ---- Stage 3: N=128 ----
    transpose_dup<<<dim3(SS2/32, MM/32), tb>>>(C2, C2d, MM, SS2);
    gemm_x2<128><<<dim3(MM/32, SS3/128, EE), 256, SMEM128>>>(
        C2d, W3t, H3, MM, SS3, SS2, KCHUNK);
    lif_scan4<<<(n3/4 + 255)/256, 256>>>(H3, g3, nullptr, out + n1 + n2, SS3);
}